// round 1
// baseline (speedup 1.0000x reference)
#include <cuda_runtime.h>
#include <math.h>

#define Gn  2
#define Nn  20000
#define En  160000
#define E2n 180000
#define Fn  128
#define Hn  8
#define Cn  64
#define HCn 512

// ---------------- device scratch (allocation-free) ----------------
__device__ float d_xl1[Gn * Nn * HCn];
__device__ float d_xr1[Gn * Nn * HCn];
__device__ float d_h1 [Gn * Nn * HCn];
__device__ float d_loop[Gn * Nn];
__device__ float d_cnt [Gn * Nn];
__device__ float d_logit1[Gn * E2n * Hn];
__device__ float d_max1[Gn * Nn * Hn];
__device__ float d_den1[Gn * Nn * Hn];
__device__ float d_xl2[Gn * Nn * Cn];
__device__ float d_xr2[Gn * Nn * Cn];
__device__ float d_h2 [Gn * Nn * Cn];
__device__ float d_logit2[Gn * E2n];
__device__ float d_max2[Gn * Nn];
__device__ float d_den2[Gn * Nn];
__device__ float d_hfin[Gn * Nn * Cn];
__device__ float d_gmax[Cn];
__device__ float d_tail[Cn];

// ---------------- helpers ----------------
__device__ __forceinline__ void atomicMaxFloat(float* addr, float val) {
    if (val >= 0.0f)
        atomicMax((int*)addr, __float_as_int(val));
    else
        atomicMin((unsigned int*)addr, __float_as_uint(val));
}

__device__ __forceinline__ float warpReduceSum(float v) {
#pragma unroll
    for (int o = 16; o; o >>= 1) v += __shfl_xor_sync(0xffffffffu, v, o);
    return v;
}

// ---------------- init ----------------
__global__ void k_init() {
    size_t i = (size_t)blockIdx.x * blockDim.x + threadIdx.x;
    size_t stride = (size_t)gridDim.x * blockDim.x;
    for (size_t t = i; t < (size_t)Gn * Nn * HCn; t += stride) d_h1[t] = 0.0f;
    for (size_t t = i; t < (size_t)Gn * Nn * Cn;  t += stride) d_h2[t] = 0.0f;
    for (size_t t = i; t < (size_t)Gn * Nn * Hn;  t += stride) { d_max1[t] = -INFINITY; d_den1[t] = 0.0f; }
    for (size_t t = i; t < (size_t)Gn * Nn;       t += stride) {
        d_cnt[t] = 0.0f; d_loop[t] = 0.0f; d_max2[t] = -INFINITY; d_den2[t] = 0.0f;
    }
    for (size_t t = i; t < (size_t)Cn; t += stride) d_gmax[t] = -INFINITY;
}

// ---------------- self-loop edge attr ----------------
__global__ void k_loop_sum(const int* __restrict__ ei, const float* __restrict__ ew) {
    int i = blockIdx.x * blockDim.x + threadIdx.x;
    if (i >= Gn * En) return;
    int g = i / En, e = i % En;
    int dst = ei[g * 2 * En + En + e];
    atomicAdd(&d_cnt [g * Nn + dst], 1.0f);
    atomicAdd(&d_loop[g * Nn + dst], ew[g * En + e]);
}

__global__ void k_loop_div() {
    int i = blockIdx.x * blockDim.x + threadIdx.x;
    if (i >= Gn * Nn) return;
    d_loop[i] = d_loop[i] / fmaxf(d_cnt[i], 1.0f);
}

// ---------------- SGEMM: Out[M,Nc] = A[M,K] @ W[K,Nc] + bias ----------------
// Requires M%64==0, Nc%64==0, K%16==0 (true for all uses here).
__global__ void sgemm_bias(const float* __restrict__ A, const float* __restrict__ W,
                           const float* __restrict__ bias, float* __restrict__ Out,
                           int M, int K, int Nc) {
    __shared__ float As[16][64];
    __shared__ float Ws[16][64];
    int tid = threadIdx.x;                     // 256 threads
    int bm = blockIdx.y * 64, bn = blockIdx.x * 64;
    int tx = tid & 15, ty = tid >> 4;          // 16x16 thread grid, 4x4 microtile
    int am = tid >> 2;                         // 0..63
    int ak = (tid & 3) * 4;                    // 0,4,8,12
    int wk = tid >> 4;                         // 0..15
    int wn = (tid & 15) * 4;                   // 0..60

    float acc[4][4] = {};
    for (int k0 = 0; k0 < K; k0 += 16) {
        float4 av = *(const float4*)&A[(size_t)(bm + am) * K + k0 + ak];
        As[ak + 0][am] = av.x; As[ak + 1][am] = av.y;
        As[ak + 2][am] = av.z; As[ak + 3][am] = av.w;
        float4 wv = *(const float4*)&W[(size_t)(k0 + wk) * Nc + bn + wn];
        *(float4*)&Ws[wk][wn] = wv;
        __syncthreads();
#pragma unroll
        for (int kk = 0; kk < 16; kk++) {
            float4 a = *(float4*)&As[kk][ty * 4];
            float4 w = *(float4*)&Ws[kk][tx * 4];
            float ar[4] = {a.x, a.y, a.z, a.w};
            float wr[4] = {w.x, w.y, w.z, w.w};
#pragma unroll
            for (int i = 0; i < 4; i++)
#pragma unroll
                for (int j = 0; j < 4; j++) acc[i][j] += ar[i] * wr[j];
        }
        __syncthreads();
    }
#pragma unroll
    for (int i = 0; i < 4; i++) {
        int m = bm + ty * 4 + i;
#pragma unroll
        for (int j = 0; j < 4; j++) {
            int n = bn + tx * 4 + j;
            Out[(size_t)m * Nc + n] = acc[i][j] + bias[n];
        }
    }
}

// ---------------- layer 1: edge logits + segment max ----------------
__global__ void k_edge_logit1(const int* __restrict__ ei, const float* __restrict__ ew,
                              const float* __restrict__ We1, const float* __restrict__ att1) {
    int wid  = (blockIdx.x * blockDim.x + threadIdx.x) >> 5;
    int lane = threadIdx.x & 31;
    if (wid >= Gn * E2n) return;
    int g = wid / E2n, e = wid % E2n;
    int s, d; float a;
    if (e < En) {
        s = ei[g * 2 * En + e];
        d = ei[g * 2 * En + En + e];
        a = ew[g * En + e];
    } else {
        s = d = e - En;
        a = d_loop[g * Nn + s];
    }
    const float* xl = d_xl1 + (size_t)(g * Nn + s) * HCn;
    const float* xr = d_xr1 + (size_t)(g * Nn + d) * HCn;
    size_t eb = (size_t)(g * E2n + e) * Hn;
    int    db = (g * Nn + d) * Hn;
#pragma unroll
    for (int h = 0; h < Hn; h++) {
        float p = 0.0f;
#pragma unroll
        for (int t = 0; t < 2; t++) {
            int j = h * 64 + t * 32 + lane;
            float v = xl[j] + xr[j] + a * We1[j];
            v = v > 0.0f ? v : 0.2f * v;
            p += v * att1[j];
        }
        p = warpReduceSum(p);
        if (lane == 0) {
            d_logit1[eb + h] = p;
            atomicMaxFloat(&d_max1[db + h], p);
        }
    }
}

__global__ void k_softmax_exp1(const int* __restrict__ ei) {
    int i = blockIdx.x * blockDim.x + threadIdx.x;
    if (i >= Gn * E2n * Hn) return;
    int h = i & (Hn - 1);
    int ge = i >> 3;
    int g = ge / E2n, e = ge % E2n;
    int d = (e < En) ? ei[g * 2 * En + En + e] : (e - En);
    float ex = __expf(d_logit1[i] - d_max1[(g * Nn + d) * Hn + h]);
    d_logit1[i] = ex;
    atomicAdd(&d_den1[(g * Nn + d) * Hn + h], ex);
}

__global__ void k_aggregate1(const int* __restrict__ ei) {
    int wid  = (blockIdx.x * blockDim.x + threadIdx.x) >> 5;
    int lane = threadIdx.x & 31;
    if (wid >= Gn * E2n) return;
    int g = wid / E2n, e = wid % E2n;
    int s, d;
    if (e < En) {
        s = ei[g * 2 * En + e];
        d = ei[g * 2 * En + En + e];
    } else {
        s = d = e - En;
    }
    size_t eb = (size_t)(g * E2n + e) * Hn;
    int    db = (g * Nn + d) * Hn;
    float alpha = 0.0f;
    if (lane < Hn) alpha = d_logit1[eb + lane] / d_den1[db + lane];
    const float* xl = d_xl1 + (size_t)(g * Nn + s) * HCn;
    float*      out = d_h1  + (size_t)(g * Nn + d) * HCn;
#pragma unroll
    for (int it = 0; it < 16; it++) {
        int j = it * 32 + lane;
        float al = __shfl_sync(0xffffffffu, alpha, it >> 1);
        atomicAdd(&out[j], al * xl[j]);
    }
}

__global__ void k_elu1(const float* __restrict__ bias1) {
    size_t i = (size_t)blockIdx.x * blockDim.x + threadIdx.x;
    size_t stride = (size_t)gridDim.x * blockDim.x;
    for (size_t t = i; t < (size_t)Gn * Nn * HCn; t += stride) {
        float v = d_h1[t] + bias1[t % HCn];
        d_h1[t] = v > 0.0f ? v : expm1f(v);
    }
}

// ---------------- layer 2 (H=1, C=64) ----------------
__global__ void k_edge_logit2(const int* __restrict__ ei, const float* __restrict__ ew,
                              const float* __restrict__ We2, const float* __restrict__ att2) {
    int wid  = (blockIdx.x * blockDim.x + threadIdx.x) >> 5;
    int lane = threadIdx.x & 31;
    if (wid >= Gn * E2n) return;
    int g = wid / E2n, e = wid % E2n;
    int s, d; float a;
    if (e < En) {
        s = ei[g * 2 * En + e];
        d = ei[g * 2 * En + En + e];
        a = ew[g * En + e];
    } else {
        s = d = e - En;
        a = d_loop[g * Nn + s];
    }
    const float* xl = d_xl2 + (size_t)(g * Nn + s) * Cn;
    const float* xr = d_xr2 + (size_t)(g * Nn + d) * Cn;
    float p = 0.0f;
#pragma unroll
    for (int t = 0; t < 2; t++) {
        int j = t * 32 + lane;
        float v = xl[j] + xr[j] + a * We2[j];
        v = v > 0.0f ? v : 0.2f * v;
        p += v * att2[j];
    }
    p = warpReduceSum(p);
    if (lane == 0) {
        d_logit2[(size_t)g * E2n + e] = p;
        atomicMaxFloat(&d_max2[g * Nn + d], p);
    }
}

__global__ void k_softmax_exp2(const int* __restrict__ ei) {
    int i = blockIdx.x * blockDim.x + threadIdx.x;
    if (i >= Gn * E2n) return;
    int g = i / E2n, e = i % E2n;
    int d = (e < En) ? ei[g * 2 * En + En + e] : (e - En);
    float ex = __expf(d_logit2[i] - d_max2[g * Nn + d]);
    d_logit2[i] = ex;
    atomicAdd(&d_den2[g * Nn + d], ex);
}

__global__ void k_aggregate2(const int* __restrict__ ei) {
    int wid  = (blockIdx.x * blockDim.x + threadIdx.x) >> 5;
    int lane = threadIdx.x & 31;
    if (wid >= Gn * E2n) return;
    int g = wid / E2n, e = wid % E2n;
    int s, d;
    if (e < En) {
        s = ei[g * 2 * En + e];
        d = ei[g * 2 * En + En + e];
    } else {
        s = d = e - En;
    }
    float alpha = d_logit2[(size_t)g * E2n + e] / d_den2[g * Nn + d];
    const float* xl = d_xl2 + (size_t)(g * Nn + s) * Cn;
    float*      out = d_h2  + (size_t)(g * Nn + d) * Cn;
#pragma unroll
    for (int t = 0; t < 2; t++) {
        int j = t * 32 + lane;
        atomicAdd(&out[j], alpha * xl[j]);
    }
}

// elu + global per-channel max (for graph embedding)
__global__ void k_elu2_max(const float* __restrict__ bias2) {
    int tid = threadIdx.x;  // 256
    size_t stride = (size_t)gridDim.x * blockDim.x;  // multiple of 64
    float lm = -INFINITY;
    for (size_t t = (size_t)blockIdx.x * blockDim.x + tid; t < (size_t)Gn * Nn * Cn; t += stride) {
        float v = d_h2[t] + bias2[t & (Cn - 1)];
        v = v > 0.0f ? v : expm1f(v);
        d_hfin[t] = v;
        lm = fmaxf(lm, v);
    }
    __shared__ float sm[256];
    sm[tid] = lm;
    __syncthreads();
    if (tid < 128) sm[tid] = fmaxf(sm[tid], sm[tid + 128]);
    __syncthreads();
    if (tid < 64) {
        float m = fmaxf(sm[tid], sm[tid + 64]);
        atomicMaxFloat(&d_gmax[tid], m);
    }
}

// Gv = relu(gmax @ Wg + bg); tail[j] = sum_k Gv[k]*Wn[64+k][j] + bn[j]
__global__ void k_graph_head(const float* __restrict__ Wg, const float* __restrict__ bg,
                             const float* __restrict__ Wnm, const float* __restrict__ bn) {
    __shared__ float gv[Cn];
    int c = threadIdx.x;  // 64
    float acc = bg[c];
#pragma unroll
    for (int k = 0; k < Cn; k++) acc += d_gmax[k] * Wg[k * Cn + c];
    gv[c] = fmaxf(acc, 0.0f);
    __syncthreads();
    float t = bn[c];
#pragma unroll
    for (int k = 0; k < Cn; k++) t += gv[k] * Wnm[(Cn + k) * Cn + c];
    d_tail[c] = t;
}

// out[gn] = relu(h[gn] @ Wn_top + tail) @ Wo + bo   (warp per node)
__global__ void k_final(const float* __restrict__ Wnm, const float* __restrict__ Wo,
                        const float* __restrict__ bo, float* __restrict__ out) {
    __shared__ float sWn[Cn * Cn];
    __shared__ float sWo[Cn];
    __shared__ float sTail[Cn];
    int tid = threadIdx.x;  // 256
    for (int i = tid; i < Cn * Cn; i += blockDim.x) sWn[i] = Wnm[i];  // top 64 rows of Wn
    if (tid < Cn) { sWo[tid] = Wo[tid]; sTail[tid] = d_tail[tid]; }
    __syncthreads();
    int warp = tid >> 5, lane = tid & 31;
    int gn = blockIdx.x * (blockDim.x >> 5) + warp;
    if (gn >= Gn * Nn) return;
    const float* hrow = d_hfin + (size_t)gn * Cn;
    float h0 = hrow[lane], h1 = hrow[lane + 32];
    float a0 = sTail[lane], a1 = sTail[lane + 32];
#pragma unroll
    for (int k = 0; k < Cn; k++) {
        float hk = __shfl_sync(0xffffffffu, (k < 32) ? h0 : h1, k & 31);
        a0 += hk * sWn[k * Cn + lane];
        a1 += hk * sWn[k * Cn + lane + 32];
    }
    float r = fmaxf(a0, 0.0f) * sWo[lane] + fmaxf(a1, 0.0f) * sWo[lane + 32];
    r = warpReduceSum(r);
    if (lane == 0) out[gn] = r + bo[0];
}

// ---------------- launch ----------------
extern "C" void kernel_launch(void* const* d_in, const int* in_sizes, int n_in,
                              void* d_out, int out_size) {
    const float* x     = (const float*)d_in[0];
    const int*   ei    = (const int*)  d_in[1];
    const float* ew    = (const float*)d_in[2];
    const float* Wl1   = (const float*)d_in[3];
    const float* bl1   = (const float*)d_in[4];
    const float* Wr1   = (const float*)d_in[5];
    const float* br1   = (const float*)d_in[6];
    const float* We1   = (const float*)d_in[7];
    const float* att1  = (const float*)d_in[8];
    const float* bias1 = (const float*)d_in[9];
    const float* Wl2   = (const float*)d_in[10];
    const float* bl2   = (const float*)d_in[11];
    const float* Wr2   = (const float*)d_in[12];
    const float* br2   = (const float*)d_in[13];
    const float* We2   = (const float*)d_in[14];
    const float* att2  = (const float*)d_in[15];
    const float* bias2 = (const float*)d_in[16];
    const float* Wg    = (const float*)d_in[17];
    const float* bg    = (const float*)d_in[18];
    const float* Wnm   = (const float*)d_in[19];
    const float* bn    = (const float*)d_in[20];
    const float* Wo    = (const float*)d_in[21];
    const float* bo    = (const float*)d_in[22];
    float* out = (float*)d_out;

    float *pxl1, *pxr1, *ph1, *pxl2, *pxr2;
    cudaGetSymbolAddress((void**)&pxl1, d_xl1);
    cudaGetSymbolAddress((void**)&pxr1, d_xr1);
    cudaGetSymbolAddress((void**)&ph1,  d_h1);
    cudaGetSymbolAddress((void**)&pxl2, d_xl2);
    cudaGetSymbolAddress((void**)&pxr2, d_xr2);

    const int M = Gn * Nn;  // 40000

    k_init<<<2048, 256>>>();
    k_loop_sum<<<(Gn * En + 255) / 256, 256>>>(ei, ew);
    k_loop_div<<<(Gn * Nn + 255) / 256, 256>>>();

    sgemm_bias<<<dim3(HCn / 64, M / 64), 256>>>(x, Wl1, bl1, pxl1, M, Fn, HCn);
    sgemm_bias<<<dim3(HCn / 64, M / 64), 256>>>(x, Wr1, br1, pxr1, M, Fn, HCn);

    {
        int warps = Gn * E2n;
        int blocks = (warps * 32 + 255) / 256;
        k_edge_logit1<<<blocks, 256>>>(ei, ew, We1, att1);
        k_softmax_exp1<<<(Gn * E2n * Hn + 255) / 256, 256>>>(ei);
        k_aggregate1<<<blocks, 256>>>(ei);
    }
    k_elu1<<<4096, 256>>>(bias1);

    sgemm_bias<<<dim3(Cn / 64, M / 64), 256>>>(ph1, Wl2, bl2, pxl2, M, HCn, Cn);
    sgemm_bias<<<dim3(Cn / 64, M / 64), 256>>>(ph1, Wr2, br2, pxr2, M, HCn, Cn);

    {
        int warps = Gn * E2n;
        int blocks = (warps * 32 + 255) / 256;
        k_edge_logit2<<<blocks, 256>>>(ei, ew, We2, att2);
        k_softmax_exp2<<<(Gn * E2n + 255) / 256, 256>>>(ei);
        k_aggregate2<<<blocks, 256>>>(ei);
    }

    k_elu2_max<<<512, 256>>>(bias2);
    k_graph_head<<<1, 64>>>(Wg, bg, Wnm, bn);
    k_final<<<(M + 7) / 8, 256>>>(Wnm, Wo, bo, out);
}